// round 2
// baseline (speedup 1.0000x reference)
#include <cuda_runtime.h>
#include <math.h>

#define N_NODES  20000
#define N_EDGES  320000
#define N_GRAPHS 1000

// ---------------- static device scratch (no allocations allowed) ----------------
__device__ float g_xl[N_NODES * 256];
__device__ float g_xr[N_NODES * 256];
__device__ float g_hA[N_NODES * 256];
__device__ float g_hB[N_NODES * 256];
__device__ int   g_deg[N_NODES];
__device__ int   g_rowptr[N_NODES + 1];
__device__ int   g_cursor[N_NODES];
__device__ int   g_csr[N_EDGES];
__device__ float g_sums[N_GRAPHS * 64];
__device__ int   g_cnt[N_GRAPHS];

// ---------------- utility kernels ----------------
__global__ void zero_i32(int* p, int n) {
    int i = blockIdx.x * blockDim.x + threadIdx.x;
    if (i < n) p[i] = 0;
}
__global__ void zero_f32(float* p, int n) {
    int i = blockIdx.x * blockDim.x + threadIdx.x;
    if (i < n) p[i] = 0.f;
}

__global__ void hist_k(const int* __restrict__ dst, int* __restrict__ deg) {
    int e = blockIdx.x * blockDim.x + threadIdx.x;
    if (e < N_EDGES) atomicAdd(&deg[dst[e]], 1);
}

// single-block exclusive scan over N_NODES degrees -> rowptr, cursor
__global__ void scan_k(const int* __restrict__ deg, int* __restrict__ rowptr,
                       int* __restrict__ cursor) {
    __shared__ int sh[1024];
    const int CH = 20;  // 1024*20 = 20480 >= 20000
    int t = threadIdx.x;
    int base = t * CH;
    int loc[CH];
    int s = 0;
    #pragma unroll
    for (int i = 0; i < CH; i++) {
        int idx = base + i;
        int v = (idx < N_NODES) ? deg[idx] : 0;
        loc[i] = s;
        s += v;
    }
    sh[t] = s;
    __syncthreads();
    for (int off = 1; off < 1024; off <<= 1) {
        int v = (t >= off) ? sh[t - off] : 0;
        __syncthreads();
        sh[t] += v;
        __syncthreads();
    }
    int pre = (t > 0) ? sh[t - 1] : 0;
    #pragma unroll
    for (int i = 0; i < CH; i++) {
        int idx = base + i;
        if (idx < N_NODES) {
            int v = pre + loc[i];
            rowptr[idx] = v;
            cursor[idx] = v;
        }
    }
    if (t == 1023) rowptr[N_NODES] = sh[1023];
}

__global__ void scatter_k(const int* __restrict__ dst, int* __restrict__ cursor,
                          int* __restrict__ csr) {
    int e = blockIdx.x * blockDim.x + threadIdx.x;
    if (e < N_EDGES) {
        int p = atomicAdd(&cursor[dst[e]], 1);
        csr[p] = e;
    }
}

// ---------------- layer-1 GEMM (K=12, Ncols=256) ----------------
__global__ void gemm_k12(const float* __restrict__ x, const float* __restrict__ W,
                         const float* __restrict__ b, float* __restrict__ out) {
    __shared__ float Ws[12 * 256];
    __shared__ float xs[32 * 12];
    int tid = threadIdx.x;           // 256 threads, thread = output column
    int r0 = blockIdx.x * 32;
    for (int i = tid; i < 12 * 256; i += 256) Ws[i] = W[i];
    for (int i = tid; i < 32 * 12; i += 256) {
        int r = r0 + i / 12;
        xs[i] = (r < N_NODES) ? x[(size_t)r * 12 + (i % 12)] : 0.f;
    }
    __syncthreads();
    float bb = b[tid];
    for (int r = 0; r < 32; r++) {
        int gr = r0 + r;
        if (gr >= N_NODES) break;
        float acc = bb;
        #pragma unroll
        for (int k = 0; k < 12; k++) acc += xs[r * 12 + k] * Ws[k * 256 + tid];
        out[(size_t)gr * 256 + tid] = acc;
    }
}

// ---------------- tiled SGEMM: C[M,Ncols] = A[M,K] @ W[K,Ncols] + bias ----------------
// BM=BN=64, BK=8, 256 threads, 4x4 microtile
__global__ void sgemm64(const float* __restrict__ A, const float* __restrict__ W,
                        const float* __restrict__ bias, float* __restrict__ C,
                        int M, int K, int Ncols) {
    __shared__ __align__(16) float As[8][64];
    __shared__ __align__(16) float Bs[8][64];
    int tid = threadIdx.x;
    int tx = tid & 15;
    int ty = tid >> 4;
    int row0 = blockIdx.y * 64;
    int col0 = blockIdx.x * 64;

    int ar = tid >> 2;          // 0..63 (tile row for A load)
    int ak = (tid & 3) * 2;     // 0,2,4,6 (k offset for A load)
    int bk = tid >> 5;          // 0..7  (k row for B load)
    int bc = (tid & 31) * 2;    // 0..62 (col offset for B load)

    float acc[4][4];
    #pragma unroll
    for (int i = 0; i < 4; i++)
        #pragma unroll
        for (int j = 0; j < 4; j++) acc[i][j] = 0.f;

    int arow = row0 + ar;
    const float* Aptr = A + (size_t)arow * K + ak;
    const float* Wptr = W + (size_t)bk * Ncols + col0 + bc;

    for (int k0 = 0; k0 < K; k0 += 8) {
        float2 av = make_float2(0.f, 0.f);
        if (arow < M) av = *(const float2*)(Aptr + k0);
        float2 bv = *(const float2*)(Wptr + (size_t)k0 * Ncols);
        As[ak][ar] = av.x;
        As[ak + 1][ar] = av.y;
        Bs[bk][bc] = bv.x;
        Bs[bk][bc + 1] = bv.y;
        __syncthreads();
        #pragma unroll
        for (int kk = 0; kk < 8; kk++) {
            float4 ra4 = *(const float4*)(&As[kk][ty * 4]);
            float4 rb4 = *(const float4*)(&Bs[kk][tx * 4]);
            float ra[4] = {ra4.x, ra4.y, ra4.z, ra4.w};
            float rb[4] = {rb4.x, rb4.y, rb4.z, rb4.w};
            #pragma unroll
            for (int i = 0; i < 4; i++)
                #pragma unroll
                for (int j = 0; j < 4; j++) acc[i][j] += ra[i] * rb[j];
        }
        __syncthreads();
    }
    #pragma unroll
    for (int i = 0; i < 4; i++) {
        int r = row0 + ty * 4 + i;
        if (r < M) {
            #pragma unroll
            for (int j = 0; j < 4; j++) {
                int c = col0 + tx * 4 + j;
                C[(size_t)r * Ncols + c] = acc[i][j] + bias[c];
            }
        }
    }
}

// ---------------- fused edge aggregation: one warp per (node, head) ----------------
// online softmax over incoming edges, edge embedding (ea @ We) computed on the fly
template <int H, bool ELU>
__global__ void edge_agg(const int* __restrict__ rowptr, const int* __restrict__ csr,
                         const int* __restrict__ src, const float* __restrict__ ea,
                         const float* __restrict__ xl, const float* __restrict__ xr,
                         const float* __restrict__ We, const float* __restrict__ att,
                         const float* __restrict__ bias, float* __restrict__ out) {
    const int D = H * 64;
    int w = (blockIdx.x * blockDim.x + threadIdx.x) >> 5;
    int lane = threadIdx.x & 31;
    int n = w / H;
    int h = w - n * H;
    if (n >= N_NODES) return;

    int c0 = h * 64 + lane;
    int c1 = c0 + 32;
    float xr0 = xr[(size_t)n * D + c0];
    float xr1 = xr[(size_t)n * D + c1];
    float at0 = att[h * 64 + lane];
    float at1 = att[h * 64 + lane + 32];
    float we0[4], we1[4];
    #pragma unroll
    for (int f = 0; f < 4; f++) {
        we0[f] = We[f * D + c0];
        we1[f] = We[f * D + c1];
    }

    float m = -INFINITY, s = 0.f, a0 = 0.f, a1 = 0.f;
    int beg = rowptr[n], end = rowptr[n + 1];
    for (int i = beg; i < end; i++) {
        int e = csr[i];
        int sn = src[e];
        float4 eav = *(const float4*)(ea + (size_t)e * 4);
        float xl0 = xl[(size_t)sn * D + c0];
        float xl1 = xl[(size_t)sn * D + c1];
        float z0 = xl0 + xr0 + eav.x * we0[0] + eav.y * we0[1] + eav.z * we0[2] + eav.w * we0[3];
        float z1 = xl1 + xr1 + eav.x * we1[0] + eav.y * we1[1] + eav.z * we1[2] + eav.w * we1[3];
        z0 = z0 > 0.f ? z0 : 0.2f * z0;   // leaky_relu(0.2)
        z1 = z1 > 0.f ? z1 : 0.2f * z1;
        float t = z0 * at0 + z1 * at1;
        #pragma unroll
        for (int o = 16; o > 0; o >>= 1) t += __shfl_xor_sync(0xFFFFFFFFu, t, o);
        float mn = fmaxf(m, t);
        float sc = __expf(m - mn);        // 0 on first iteration (m = -inf)
        float p = __expf(t - mn);
        s = s * sc + p;
        a0 = a0 * sc + p * xl0;
        a1 = a1 * sc + p * xl1;
        m = mn;
    }
    float inv = 1.f / (s + 1e-16f);
    float r0 = a0 * inv + bias[c0];
    float r1 = a1 * inv + bias[c1];
    if (ELU) {
        r0 = r0 > 0.f ? r0 : expm1f(r0);
        r1 = r1 > 0.f ? r1 : expm1f(r1);
    }
    out[(size_t)n * D + c0] = r0;
    out[(size_t)n * D + c1] = r1;
}

// ---------------- global mean pool ----------------
__global__ void pool_k(const float* __restrict__ h, const int* __restrict__ batch,
                       float* __restrict__ sums, int* __restrict__ cnt) {
    int idx = blockIdx.x * blockDim.x + threadIdx.x;
    if (idx >= N_NODES * 64) return;
    int n = idx >> 6;
    int c = idx & 63;
    int g = batch[n];
    atomicAdd(&sums[g * 64 + c], h[idx]);
    if (c == 0) atomicAdd(&cnt[g], 1);
}

// ---------------- MLP head, one block (64 threads) per graph ----------------
__global__ void mlp_k(const float* __restrict__ sums, const int* __restrict__ cnt,
                      const float* __restrict__ mW1, const float* __restrict__ mb1,
                      const float* __restrict__ mW2, const float* __restrict__ mb2,
                      const float* __restrict__ mW3, const float* __restrict__ mb3,
                      float* __restrict__ out) {
    __shared__ float gv[64];
    __shared__ float h1[32];
    __shared__ float h2[16];
    int g = blockIdx.x, t = threadIdx.x;
    float cf = fmaxf((float)cnt[g], 1.f);
    gv[t] = sums[g * 64 + t] / cf;
    __syncthreads();
    if (t < 32) {
        float a = mb1[t];
        #pragma unroll
        for (int k = 0; k < 64; k++) a += gv[k] * mW1[k * 32 + t];
        h1[t] = fmaxf(a, 0.f);
    }
    __syncthreads();
    if (t < 16) {
        float a = mb2[t];
        #pragma unroll
        for (int k = 0; k < 32; k++) a += h1[k] * mW2[k * 16 + t];
        h2[t] = fmaxf(a, 0.f);
    }
    __syncthreads();
    if (t < 4) {
        float a = mb3[t];
        #pragma unroll
        for (int k = 0; k < 16; k++) a += h2[k] * mW3[k * 4 + t];
        out[g * 4 + t] = a;
    }
}

// ---------------- launch ----------------
extern "C" void kernel_launch(void* const* d_in, const int* in_sizes, int n_in,
                              void* d_out, int out_size) {
    (void)in_sizes; (void)n_in; (void)out_size;
    const float* x     = (const float*)d_in[0];
    const int*   ei    = (const int*)d_in[1];
    const float* ea    = (const float*)d_in[2];
    const int*   batch = (const int*)d_in[3];
    const float* Wl1 = (const float*)d_in[4],  *bl1 = (const float*)d_in[5];
    const float* Wr1 = (const float*)d_in[6],  *br1 = (const float*)d_in[7];
    const float* We1 = (const float*)d_in[8],  *att1 = (const float*)d_in[9],  *bias1 = (const float*)d_in[10];
    const float* Wl2 = (const float*)d_in[11], *bl2 = (const float*)d_in[12];
    const float* Wr2 = (const float*)d_in[13], *br2 = (const float*)d_in[14];
    const float* We2 = (const float*)d_in[15], *att2 = (const float*)d_in[16], *bias2 = (const float*)d_in[17];
    const float* Wl3 = (const float*)d_in[18], *bl3 = (const float*)d_in[19];
    const float* Wr3 = (const float*)d_in[20], *br3 = (const float*)d_in[21];
    const float* We3 = (const float*)d_in[22], *att3 = (const float*)d_in[23], *bias3 = (const float*)d_in[24];
    const float* mW1 = (const float*)d_in[25], *mb1 = (const float*)d_in[26];
    const float* mW2 = (const float*)d_in[27], *mb2 = (const float*)d_in[28];
    const float* mW3 = (const float*)d_in[29], *mb3 = (const float*)d_in[30];
    float* out = (float*)d_out;

    const int* srcp = ei;
    const int* dstp = ei + N_EDGES;

    float *xl, *xr, *hA, *hB, *sums;
    int *deg, *rowptr, *cursor, *csr, *cnt;
    cudaGetSymbolAddress((void**)&xl, g_xl);
    cudaGetSymbolAddress((void**)&xr, g_xr);
    cudaGetSymbolAddress((void**)&hA, g_hA);
    cudaGetSymbolAddress((void**)&hB, g_hB);
    cudaGetSymbolAddress((void**)&sums, g_sums);
    cudaGetSymbolAddress((void**)&deg, g_deg);
    cudaGetSymbolAddress((void**)&rowptr, g_rowptr);
    cudaGetSymbolAddress((void**)&cursor, g_cursor);
    cudaGetSymbolAddress((void**)&csr, g_csr);
    cudaGetSymbolAddress((void**)&cnt, g_cnt);

    // ---- CSR by destination (shared by all 3 layers) ----
    zero_i32<<<(N_NODES + 255) / 256, 256>>>(deg, N_NODES);
    hist_k<<<(N_EDGES + 255) / 256, 256>>>(dstp, deg);
    scan_k<<<1, 1024>>>(deg, rowptr, cursor);
    scatter_k<<<(N_EDGES + 255) / 256, 256>>>(dstp, cursor, csr);

    // ---- layer 1 (K=12 -> 256, H=4) ----
    gemm_k12<<<(N_NODES + 31) / 32, 256>>>(x, Wl1, bl1, xl);
    gemm_k12<<<(N_NODES + 31) / 32, 256>>>(x, Wr1, br1, xr);
    edge_agg<4, true><<<10000, 256>>>(rowptr, csr, srcp, ea, xl, xr, We1, att1, bias1, hA);

    // ---- layer 2 (256 -> 256, H=4) ----
    sgemm64<<<dim3(4, 313), 256>>>(hA, Wl2, bl2, xl, N_NODES, 256, 256);
    sgemm64<<<dim3(4, 313), 256>>>(hA, Wr2, br2, xr, N_NODES, 256, 256);
    edge_agg<4, true><<<10000, 256>>>(rowptr, csr, srcp, ea, xl, xr, We2, att2, bias2, hB);

    // ---- layer 3 (256 -> 64, H=1, no ELU) ----
    sgemm64<<<dim3(1, 313), 256>>>(hB, Wl3, bl3, xl, N_NODES, 256, 64);
    sgemm64<<<dim3(1, 313), 256>>>(hB, Wr3, br3, xr, N_NODES, 256, 64);
    edge_agg<1, false><<<2500, 256>>>(rowptr, csr, srcp, ea, xl, xr, We3, att3, bias3, hA);

    // ---- global mean pool + MLP head ----
    zero_f32<<<(N_GRAPHS * 64 + 255) / 256, 256>>>(sums, N_GRAPHS * 64);
    zero_i32<<<(N_GRAPHS + 255) / 256, 256>>>(cnt, N_GRAPHS);
    pool_k<<<(N_NODES * 64 + 255) / 256, 256>>>(hA, batch, sums, cnt);
    mlp_k<<<N_GRAPHS, 64>>>(sums, cnt, mW1, mb1, mW2, mb2, mW3, mb3, out);
}